// round 2
// baseline (speedup 1.0000x reference)
#include <cuda_runtime.h>
#include <math.h>

// Problem constants (fixed by setup_inputs)
#define BQ      1024
#define DDIM    128
#define NKEYS   200000
#define HFDIM   168          // 24*7
#define TOPK    16
#define MT      64           // query tile
#define NT      64           // key tile
#define CHUNK   2048         // keys per block-chunk (top-k reduction granularity)
#define NCHUNKS 98           // ceil(200000/2048)
#define QTILES  (BQ/MT)      // 16

// ---------------- scratch (no allocation allowed) ----------------
__device__ float g_qn[BQ * DDIM];
__device__ float g_scale[NKEYS];
__device__ unsigned long long g_cand[(size_t)BQ * NCHUNKS * TOPK];
__device__ int g_ts64;

// ---------------- helpers ----------------
__device__ __forceinline__ unsigned int fkey(float f) {
    unsigned int u = __float_as_uint(f);
    return (u & 0x80000000u) ? ~u : (u | 0x80000000u);
}
__device__ __forceinline__ float funkey(unsigned int u) {
    return (u & 0x80000000u) ? __uint_as_float(u ^ 0x80000000u)
                             : __uint_as_float(~u);
}

#define FMA2(acc, a, b) \
    asm("fma.rn.f32x2 %0, %1, %2, %0;" : "+l"(acc) : "l"(a), "l"(b))
#define UNPK(lo, hi, v) \
    asm("mov.b64 {%0,%1}, %2;" : "=f"(lo), "=f"(hi) : "l"(v))

#define NEG_INF __int_as_float(0xff800000)

// ---------------- kernel 0: detect timestamp dtype ----------------
__global__ void k_detect(const unsigned int* tsw) {
    if (threadIdx.x == 0) {
        int all0 = 1;
        for (int i = 0; i < 64; i++)
            if (tsw[2 * i + 1] != 0u) { all0 = 0; break; }
        g_ts64 = all0;   // int64 timestamps (high words all zero)
    }
}

// ---------------- kernel 1: normalize queries ----------------
__global__ void k_normq(const float* __restrict__ query) {
    int b = blockIdx.x;
    int d = threadIdx.x;     // 128 threads
    float v = query[b * DDIM + d];
    float s = v * v;
    #pragma unroll
    for (int o = 16; o; o >>= 1) s += __shfl_xor_sync(0xffffffffu, s, o);
    __shared__ float ws[4];
    if ((d & 31) == 0) ws[d >> 5] = s;
    __syncthreads();
    float tot = ws[0] + ws[1] + ws[2] + ws[3];
    float n = fmaxf(sqrtf(tot), 1e-12f);
    g_qn[b * DDIM + d] = v / n;
}

// ---------------- kernel 2: per-key scale = decay / ||k|| ----------------
__global__ void k_scale(const float* __restrict__ keys, const void* ts,
                        const int* gsp, int has_gs) {
    int gw = (blockIdx.x * blockDim.x + threadIdx.x) >> 5;
    int lane = threadIdx.x & 31;
    if (gw >= NKEYS) return;
    float4 a = ((const float4*)(keys + (size_t)gw * DDIM))[lane];
    float s = a.x * a.x + a.y * a.y + a.z * a.z + a.w * a.w;
    #pragma unroll
    for (int o = 16; o; o >>= 1) s += __shfl_xor_sync(0xffffffffu, s, o);
    if (lane == 0) {
        long long t = g_ts64 ? ((const long long*)ts)[gw]
                             : (long long)((const int*)ts)[gw];
        int gs = has_gs ? gsp[0] : 1000;
        float age = (float)(gs - (int)t);
        float dec = powf(0.995f, age);
        float nr = fmaxf(sqrtf(s), 1e-12f);
        g_scale[gw] = dec / nr;
    }
}

// ---------------- kernel 3: fused GEMM (fp32 via f32x2) + chunk top-16 ----
// SMEM union: [Qs2 duplicated float2 | Ks floats]  overlapped with  [Sim]
#define QS2_ELEMS (32 * 65)                 // float2
#define QS2_BYTES (QS2_ELEMS * 8)           // 16640
#define KS_OFF    QS2_BYTES                 // 16-aligned
#define KS_BYTES  (32 * 68 * 4)             // 8704
#define UNI_BYTES (QS2_BYTES + KS_BYTES)    // 25344

__global__ void __launch_bounds__(256, 3)
k_gemm_topk(const float* __restrict__ keys) {
    __shared__ __align__(16) unsigned char s_uni[UNI_BYTES];
    __shared__ float Ss[64];
    __shared__ float topv[64][TOPK];
    __shared__ int   topi[64][TOPK];

    float2* Qs2 = (float2*)s_uni;                 // [32][65]
    float*  Ks  = (float*)(s_uni + KS_OFF);       // [32][68]
    float*  Sim = (float*)s_uni;                  // [64][65] (overlaps Qs2/Ks)

    int tid = threadIdx.x;
    int tx = tid & 15, ty = tid >> 4;
    int qtile = blockIdx.x;            // 0..15 (fast dim -> chunk L2 reuse)
    int chunk = blockIdx.y;            // 0..97
    int qbase = qtile * MT;
    int c0 = chunk * CHUNK;
    int nkeys_c = min(CHUNK, NKEYS - c0);
    int nsub = nkeys_c >> 6;           // N % 64 == 0

    if (tid < 64) {
        #pragma unroll
        for (int j = 0; j < TOPK; j++) { topv[tid][j] = NEG_INF; topi[tid][j] = 0; }
    }

    for (int sub = 0; sub < nsub; ++sub) {
        int n0 = c0 + sub * 64;
        __syncthreads();                       // prior scan / Ss reads done
        if (tid < 64) Ss[tid] = g_scale[n0 + tid];

        unsigned long long acc[4][2];
        #pragma unroll
        for (int i = 0; i < 4; i++) { acc[i][0] = 0ull; acc[i][1] = 0ull; }

        int kq = tid >> 3;                     // 0..31
        int dl = (tid & 7) * 4;                // 0..28

        #pragma unroll
        for (int stage = 0; stage < 4; ++stage) {
            int ds = stage * 32;
            __syncthreads();                   // prior-stage FMAs done
            // load Q tile (duplicated pairs) and K tile, transposed [d][x]
            {
                const float4 q0 = *(const float4*)&g_qn[(qbase + kq) * DDIM + ds + dl];
                const float4 q1 = *(const float4*)&g_qn[(qbase + kq + 32) * DDIM + ds + dl];
                Qs2[(dl + 0) * 65 + kq]      = make_float2(q0.x, q0.x);
                Qs2[(dl + 1) * 65 + kq]      = make_float2(q0.y, q0.y);
                Qs2[(dl + 2) * 65 + kq]      = make_float2(q0.z, q0.z);
                Qs2[(dl + 3) * 65 + kq]      = make_float2(q0.w, q0.w);
                Qs2[(dl + 0) * 65 + kq + 32] = make_float2(q1.x, q1.x);
                Qs2[(dl + 1) * 65 + kq + 32] = make_float2(q1.y, q1.y);
                Qs2[(dl + 2) * 65 + kq + 32] = make_float2(q1.z, q1.z);
                Qs2[(dl + 3) * 65 + kq + 32] = make_float2(q1.w, q1.w);
                const float4 k0 = *(const float4*)&keys[(size_t)(n0 + kq) * DDIM + ds + dl];
                const float4 k1 = *(const float4*)&keys[(size_t)(n0 + kq + 32) * DDIM + ds + dl];
                Ks[(dl + 0) * 68 + kq]      = k0.x;
                Ks[(dl + 1) * 68 + kq]      = k0.y;
                Ks[(dl + 2) * 68 + kq]      = k0.z;
                Ks[(dl + 3) * 68 + kq]      = k0.w;
                Ks[(dl + 0) * 68 + kq + 32] = k1.x;
                Ks[(dl + 1) * 68 + kq + 32] = k1.y;
                Ks[(dl + 2) * 68 + kq + 32] = k1.z;
                Ks[(dl + 3) * 68 + kq + 32] = k1.w;
            }
            __syncthreads();
            #pragma unroll
            for (int d = 0; d < 32; ++d) {
                unsigned long long a0 = *(const unsigned long long*)&Qs2[d * 65 + ty * 4 + 0];
                unsigned long long a1 = *(const unsigned long long*)&Qs2[d * 65 + ty * 4 + 1];
                unsigned long long a2 = *(const unsigned long long*)&Qs2[d * 65 + ty * 4 + 2];
                unsigned long long a3 = *(const unsigned long long*)&Qs2[d * 65 + ty * 4 + 3];
                ulonglong2 bb = *(const ulonglong2*)&Ks[d * 68 + tx * 4];
                FMA2(acc[0][0], a0, bb.x); FMA2(acc[0][1], a0, bb.y);
                FMA2(acc[1][0], a1, bb.x); FMA2(acc[1][1], a1, bb.y);
                FMA2(acc[2][0], a2, bb.x); FMA2(acc[2][1], a2, bb.y);
                FMA2(acc[3][0], a3, bb.x); FMA2(acc[3][1], a3, bb.y);
            }
        }
        __syncthreads();                       // FMAs done before Sim overwrites union

        // scaled sims -> Sim[64][65]
        #pragma unroll
        for (int i = 0; i < 4; i++) {
            int q = ty * 4 + i;
            #pragma unroll
            for (int j = 0; j < 2; j++) {
                float s0, s1;
                UNPK(s0, s1, acc[i][j]);
                int k = tx * 4 + j * 2;
                Sim[q * 65 + k]     = s0 * Ss[k];
                Sim[q * 65 + k + 1] = s1 * Ss[k + 1];
            }
        }
        __syncthreads();

        // per-query serial scan + insertion top-16 (thread t owns query t)
        if (tid < 64) {
            float thr = topv[tid][TOPK - 1];
            for (int j = 0; j < 64; j++) {
                float v = Sim[tid * 65 + j];
                if (v > thr) {
                    int kidx = n0 + j;
                    int pos = TOPK - 1;
                    while (pos > 0 && topv[tid][pos - 1] < v) {
                        topv[tid][pos] = topv[tid][pos - 1];
                        topi[tid][pos] = topi[tid][pos - 1];
                        pos--;
                    }
                    topv[tid][pos] = v;
                    topi[tid][pos] = kidx;
                    thr = topv[tid][TOPK - 1];
                }
            }
        }
    }
    __syncthreads();

    if (tid < 64) {
        int b = qbase + tid;
        unsigned long long* dst = &g_cand[((size_t)b * NCHUNKS + chunk) * TOPK];
        #pragma unroll
        for (int j = 0; j < TOPK; j++) {
            unsigned long long hv = (unsigned long long)fkey(topv[tid][j]) << 32;
            dst[j] = hv | (unsigned long long)(0xFFFFFFFFu - (unsigned int)topi[tid][j]);
        }
    }
}

// ---------------- kernel 4: merge candidates + weighted gather ----------
#define NCAND (NCHUNKS * TOPK)   // 1568

__global__ void __launch_bounds__(256)
k_merge(const float* __restrict__ values, float* __restrict__ out) {
    __shared__ unsigned long long cb[NCAND];
    __shared__ unsigned long long red[256];
    __shared__ float smv[TOPK];
    __shared__ int   sidx[TOPK];
    __shared__ float w[TOPK];

    int b = blockIdx.x, tid = threadIdx.x;
    const unsigned long long* src = &g_cand[(size_t)b * NCAND];
    for (int i = tid; i < NCAND; i += 256) cb[i] = src[i];
    __syncthreads();

    for (int r = 0; r < TOPK; r++) {
        unsigned long long m = 0ull;
        for (int i = tid; i < NCAND; i += 256) {
            unsigned long long v = cb[i];
            if (v > m) m = v;
        }
        red[tid] = m;
        __syncthreads();
        #pragma unroll
        for (int s = 128; s > 0; s >>= 1) {
            if (tid < s && red[tid + s] > red[tid]) red[tid] = red[tid + s];
            __syncthreads();
        }
        unsigned long long top = red[0];
        for (int i = tid; i < NCAND; i += 256)
            if (cb[i] == top) cb[i] = 0ull;
        if (tid == 0) {
            float s = funkey((unsigned int)(top >> 32));
            int idx = (int)(0xFFFFFFFFu - (unsigned int)(top & 0xFFFFFFFFu));
            smv[r] = (s >= 0.0f) ? s : 0.0f;   // MIN_SIMILARITY mask
            sidx[r] = idx;
        }
        __syncthreads();
    }

    if (tid == 0) {
        float su = 0.0f;
        #pragma unroll
        for (int r = 0; r < TOPK; r++) su += smv[r];
        su += 1e-8f;
        #pragma unroll
        for (int r = 0; r < TOPK; r++) w[r] = smv[r] / su;
    }
    __syncthreads();

    if (tid < HFDIM) {
        float a = 0.0f;
        #pragma unroll
        for (int r = 0; r < TOPK; r++)
            a += w[r] * values[(size_t)sidx[r] * HFDIM + tid];
        out[(size_t)b * HFDIM + tid] = a;
    }
}

// ---------------- launch ----------------
extern "C" void kernel_launch(void* const* d_in, const int* in_sizes, int n_in,
                              void* d_out, int out_size) {
    const float* query  = (const float*)d_in[0];
    const float* keys   = (const float*)d_in[1];
    const float* values = (const float*)d_in[2];
    const void*  ts     = d_in[3];
    const int*   gsp    = (n_in > 4) ? (const int*)d_in[4] : nullptr;

    k_detect<<<1, 32>>>((const unsigned int*)ts);
    k_normq<<<BQ, DDIM>>>(query);
    k_scale<<<(NKEYS * 32 + 255) / 256, 256>>>(keys, ts, gsp, gsp != nullptr);
    dim3 g(QTILES, NCHUNKS);
    k_gemm_topk<<<g, 256>>>(keys);
    k_merge<<<BQ, 256>>>(values, (float*)d_out);
}

// round 3
// speedup vs baseline: 1.0814x; 1.0814x over previous
#include <cuda_runtime.h>
#include <math.h>

// Problem constants
#define BQ      1024
#define DDIM    128
#define NKEYS   200000
#define HFDIM   168
#define TOPK    16
#define MT      128          // queries per block
#define KT      128          // keys per tile
#define CHUNK   2048         // keys per chunk (top-k granularity)
#define NCHUNKS 98
#define QTILES  (BQ/MT)      // 8
#define NPAIRS  (QTILES*NCHUNKS)   // 784
#define NTHR    128
#define GRID_P  296          // 2 blocks/SM persistent

// -------- dynamic SMEM layout (bytes) --------
// union: [Qs2 16x130 f32x2 | Ks 16x132 f32]  overlapped with  Sim[128][130]
#define OFF_KS    16640
#define OFF_SS    66560
#define OFF_TOPV  67072
#define OFF_TOPI  75776
#define OFF_WORK  84480
#define SMEM_SZ   84512

// -------- scratch --------
__device__ float g_qnT[DDIM * BQ];       // transposed normalized queries [d][b]
__device__ float g_scale[NKEYS];
__device__ unsigned long long g_cand[(size_t)BQ * NCHUNKS * TOPK];
__device__ int g_ts64;
__device__ unsigned int g_work;

// -------- helpers --------
__device__ __forceinline__ unsigned int fkey(float f) {
    unsigned int u = __float_as_uint(f);
    return (u & 0x80000000u) ? ~u : (u | 0x80000000u);
}
__device__ __forceinline__ float funkey(unsigned int u) {
    return (u & 0x80000000u) ? __uint_as_float(u ^ 0x80000000u)
                             : __uint_as_float(~u);
}
#define FMA2(acc, a, b) \
    asm("fma.rn.f32x2 %0, %1, %2, %0;" : "+l"(acc) : "l"(a), "l"(b))
#define MUL2(r, a, b) \
    asm("mul.rn.f32x2 %0, %1, %2;" : "=l"(r) : "l"(a), "l"(b))
#define NEG_INF __int_as_float(0xff800000)

// -------- kernel 0: detect ts dtype + reset work counter --------
__global__ void k_detect(const unsigned int* tsw) {
    if (threadIdx.x == 0) {
        int all0 = 1;
        for (int i = 0; i < 64; i++)
            if (tsw[2 * i + 1] != 0u) { all0 = 0; break; }
        g_ts64 = all0;
        g_work = 0u;
    }
}

// -------- kernel 1: normalize queries -> transposed --------
__global__ void k_normq(const float* __restrict__ query) {
    int b = blockIdx.x;
    int d = threadIdx.x;
    float v = query[b * DDIM + d];
    float s = v * v;
    #pragma unroll
    for (int o = 16; o; o >>= 1) s += __shfl_xor_sync(0xffffffffu, s, o);
    __shared__ float ws[4];
    if ((d & 31) == 0) ws[d >> 5] = s;
    __syncthreads();
    float tot = ws[0] + ws[1] + ws[2] + ws[3];
    float n = fmaxf(sqrtf(tot), 1e-12f);
    g_qnT[d * BQ + b] = v / n;
}

// -------- kernel 2: per-key scale = decay / ||k|| --------
__global__ void k_scale(const float* __restrict__ keys, const void* ts,
                        const int* gsp, int has_gs) {
    int gw = (blockIdx.x * blockDim.x + threadIdx.x) >> 5;
    int lane = threadIdx.x & 31;
    if (gw >= NKEYS) return;
    float4 a = ((const float4*)(keys + (size_t)gw * DDIM))[lane];
    float s = a.x * a.x + a.y * a.y + a.z * a.z + a.w * a.w;
    #pragma unroll
    for (int o = 16; o; o >>= 1) s += __shfl_xor_sync(0xffffffffu, s, o);
    if (lane == 0) {
        long long t = g_ts64 ? ((const long long*)ts)[gw]
                             : (long long)((const int*)ts)[gw];
        int gs = has_gs ? gsp[0] : 1000;
        float age = (float)(gs - (int)t);
        float dec = powf(0.995f, age);
        float nr = fmaxf(sqrtf(s), 1e-12f);
        g_scale[gw] = dec / nr;
    }
}

// -------- kernel 3: persistent fused GEMM (f32x2) + chunk top-16 --------
__global__ void __launch_bounds__(NTHR, 2)
k_gemm_topk(const float* __restrict__ keys) {
    extern __shared__ __align__(16) unsigned char sm[];
    float2* Qs2  = (float2*)sm;                   // [16][130]
    float*  Ks   = (float*)(sm + OFF_KS);         // [16][132]
    float*  Sim  = (float*)sm;                    // [128][130] (union)
    float*  Ss   = (float*)(sm + OFF_SS);         // [128]
    float*  topv = (float*)(sm + OFF_TOPV);       // [128][17]
    int*    topi = (int*)(sm + OFF_TOPI);         // [128][17]
    unsigned int* swork = (unsigned int*)(sm + OFF_WORK);

    int tid = threadIdx.x;
    int tx = tid & 7;        // 8 key groups of 16 keys
    int ty = tid >> 3;       // 16 q groups of 8 queries

    for (;;) {
        __syncthreads();
        if (tid == 0) *swork = atomicAdd(&g_work, 1u);
        __syncthreads();
        unsigned int p = *swork;
        if (p >= NPAIRS) break;
        int chunk = p >> 3;
        int qtile = p & 7;
        int qbase = qtile * MT;
        int c0 = chunk * CHUNK;

        #pragma unroll
        for (int j = 0; j < TOPK; j++) {
            topv[tid * 17 + j] = NEG_INF;
            topi[tid * 17 + j] = 0;
        }

        for (int t0 = 0; t0 < CHUNK && c0 + t0 < NKEYS; t0 += KT) {
            int n0 = c0 + t0;
            int nk = min(KT, NKEYS - n0);
            __syncthreads();       // prior scan done (Sim union reuse)
            Ss[tid] = (n0 + tid < NKEYS) ? g_scale[n0 + tid] : 0.0f;

            unsigned long long acc[8][8];
            #pragma unroll
            for (int i = 0; i < 8; i++)
                #pragma unroll
                for (int j = 0; j < 8; j++) acc[i][j] = 0ull;

            for (int stage = 0; stage < 8; ++stage) {
                int ds = stage * 16;
                __syncthreads();
                // Q: coalesced from g_qnT, duplicated-pair store
                {
                    int d = tid >> 3;          // 0..15
                    int j0 = tid & 7;
                    #pragma unroll
                    for (int i = 0; i < 4; i++) {
                        int j = j0 + 8 * i;    // float4 index in row (0..31)
                        float4 v = *(const float4*)&g_qnT[(ds + d) * BQ + qbase + j * 4];
                        float2* dst = &Qs2[d * 130 + j * 4];
                        dst[0] = make_float2(v.x, v.x);
                        dst[1] = make_float2(v.y, v.y);
                        dst[2] = make_float2(v.z, v.z);
                        dst[3] = make_float2(v.w, v.w);
                    }
                }
                // K: 4 lanes per key row, transposed store
                {
                    int c = tid & 3;
                    int r = tid >> 2;          // 0..31
                    #pragma unroll
                    for (int i = 0; i < 4; i++) {
                        int row = i * 32 + r;
                        int krow = min(n0 + row, NKEYS - 1);
                        float4 v = *(const float4*)&keys[(size_t)krow * DDIM + ds + c * 4];
                        Ks[(c * 4 + 0) * 132 + row] = v.x;
                        Ks[(c * 4 + 1) * 132 + row] = v.y;
                        Ks[(c * 4 + 2) * 132 + row] = v.z;
                        Ks[(c * 4 + 3) * 132 + row] = v.w;
                    }
                }
                __syncthreads();
                #pragma unroll
                for (int d = 0; d < 16; ++d) {
                    const ulonglong2* qp = (const ulonglong2*)(Qs2 + d * 130 + ty * 8);
                    ulonglong2 q0 = qp[0], q1 = qp[1], q2 = qp[2], q3 = qp[3];
                    unsigned long long qa[8] = {q0.x, q0.y, q1.x, q1.y,
                                                q2.x, q2.y, q3.x, q3.y};
                    const ulonglong2* kp = (const ulonglong2*)(Ks + d * 132 + tx * 16);
                    ulonglong2 k0 = kp[0], k1 = kp[1], k2 = kp[2], k3 = kp[3];
                    unsigned long long kb[8] = {k0.x, k0.y, k1.x, k1.y,
                                                k2.x, k2.y, k3.x, k3.y};
                    #pragma unroll
                    for (int i = 0; i < 8; i++)
                        #pragma unroll
                        for (int j = 0; j < 8; j++)
                            FMA2(acc[i][j], qa[i], kb[j]);
                }
            }
            __syncthreads();   // all FMAs done before Sim overwrites union

            // scale + store sims
            {
                const unsigned long long* ssp =
                    (const unsigned long long*)&Ss[tx * 16];
                #pragma unroll
                for (int i = 0; i < 8; i++) {
                    int q = ty * 8 + i;
                    #pragma unroll
                    for (int j = 0; j < 8; j++) {
                        unsigned long long r;
                        MUL2(r, acc[i][j], ssp[j]);
                        *(unsigned long long*)&Sim[q * 130 + tx * 16 + 2 * j] = r;
                    }
                }
            }
            __syncthreads();

            // per-query scan + insertion top-16 (thread owns query tid)
            {
                float thr = topv[tid * 17 + TOPK - 1];
                const float* row = &Sim[tid * 130];
                for (int j = 0; j < nk; j++) {
                    float v = row[j];
                    if (v > thr) {
                        int kidx = n0 + j;
                        int pos = TOPK - 1;
                        while (pos > 0 && topv[tid * 17 + pos - 1] < v) {
                            topv[tid * 17 + pos] = topv[tid * 17 + pos - 1];
                            topi[tid * 17 + pos] = topi[tid * 17 + pos - 1];
                            pos--;
                        }
                        topv[tid * 17 + pos] = v;
                        topi[tid * 17 + pos] = kidx;
                        thr = topv[tid * 17 + TOPK - 1];
                    }
                }
            }
        }
        __syncthreads();

        {
            int b = qbase + tid;
            unsigned long long* dst = &g_cand[((size_t)b * NCHUNKS + chunk) * TOPK];
            #pragma unroll
            for (int j = 0; j < TOPK; j++) {
                unsigned long long hv =
                    (unsigned long long)fkey(topv[tid * 17 + j]) << 32;
                dst[j] = hv | (unsigned long long)(0xFFFFFFFFu -
                                (unsigned int)topi[tid * 17 + j]);
            }
        }
    }
}

// -------- kernel 4: merge candidates + weighted gather --------
#define NCAND (NCHUNKS * TOPK)

__global__ void __launch_bounds__(256)
k_merge(const float* __restrict__ values, float* __restrict__ out) {
    __shared__ unsigned long long cb[NCAND];
    __shared__ unsigned long long red[256];
    __shared__ float smv[TOPK];
    __shared__ int   sidx[TOPK];
    __shared__ float w[TOPK];

    int b = blockIdx.x, tid = threadIdx.x;
    const unsigned long long* src = &g_cand[(size_t)b * NCAND];
    for (int i = tid; i < NCAND; i += 256) cb[i] = src[i];
    __syncthreads();

    for (int r = 0; r < TOPK; r++) {
        unsigned long long m = 0ull;
        for (int i = tid; i < NCAND; i += 256) {
            unsigned long long v = cb[i];
            if (v > m) m = v;
        }
        red[tid] = m;
        __syncthreads();
        #pragma unroll
        for (int s = 128; s > 0; s >>= 1) {
            if (tid < s && red[tid + s] > red[tid]) red[tid] = red[tid + s];
            __syncthreads();
        }
        unsigned long long top = red[0];
        for (int i = tid; i < NCAND; i += 256)
            if (cb[i] == top) cb[i] = 0ull;
        if (tid == 0) {
            float s = funkey((unsigned int)(top >> 32));
            int idx = (int)(0xFFFFFFFFu - (unsigned int)(top & 0xFFFFFFFFu));
            smv[r] = (s >= 0.0f) ? s : 0.0f;
            sidx[r] = idx;
        }
        __syncthreads();
    }

    if (tid == 0) {
        float su = 0.0f;
        #pragma unroll
        for (int r = 0; r < TOPK; r++) su += smv[r];
        su += 1e-8f;
        #pragma unroll
        for (int r = 0; r < TOPK; r++) w[r] = smv[r] / su;
    }
    __syncthreads();

    if (tid < HFDIM) {
        float a = 0.0f;
        #pragma unroll
        for (int r = 0; r < TOPK; r++)
            a += w[r] * values[(size_t)sidx[r] * HFDIM + tid];
        out[(size_t)b * HFDIM + tid] = a;
    }
}

// -------- launch --------
extern "C" void kernel_launch(void* const* d_in, const int* in_sizes, int n_in,
                              void* d_out, int out_size) {
    const float* query  = (const float*)d_in[0];
    const float* keys   = (const float*)d_in[1];
    const float* values = (const float*)d_in[2];
    const void*  ts     = d_in[3];
    const int*   gsp    = (n_in > 4) ? (const int*)d_in[4] : nullptr;

    cudaFuncSetAttribute(k_gemm_topk,
                         cudaFuncAttributeMaxDynamicSharedMemorySize, SMEM_SZ);

    k_detect<<<1, 32>>>((const unsigned int*)ts);
    k_normq<<<BQ, DDIM>>>(query);
    k_scale<<<(NKEYS * 32 + 255) / 256, 256>>>(keys, ts, gsp, gsp != nullptr);
    k_gemm_topk<<<GRID_P, NTHR, SMEM_SZ>>>(keys);
    k_merge<<<BQ, 256>>>(values, (float*)d_out);
}

// round 4
// speedup vs baseline: 1.7007x; 1.5727x over previous
#include <cuda_runtime.h>
#include <math.h>

// Problem constants
#define BQ      1024
#define DDIM    128
#define NKEYS   200000
#define HFDIM   168
#define TOPK    16
#define MT      128          // queries per block
#define KT      128          // keys per tile
#define CHUNK   2048
#define NCHUNKS 98
#define QTILES  (BQ/MT)      // 8
#define NPAIRS  (QTILES*NCHUNKS)   // 784
#define NTHR    128
#define GRID_P  296

// -------- dynamic SMEM layout (bytes) --------
// union: [Qs2 16x130 f32x2 (16640) | Ks 16x132 f32 (8448)]  overlapped with Sim[128][132] (67584)
#define OFF_KS    16640
#define OFF_SS    67584
#define OFF_TOPV  68096
#define OFF_TOPI  76800
#define OFF_WORK  85504
#define SMEM_SZ   85536

// -------- scratch --------
__device__ float g_qnT[DDIM * BQ];
__device__ float g_scale[NKEYS];
__device__ unsigned long long g_cand[(size_t)BQ * NCHUNKS * TOPK];
__device__ int g_ts64;
__device__ unsigned int g_work;

// -------- helpers --------
__device__ __forceinline__ unsigned int fkey(float f) {
    unsigned int u = __float_as_uint(f);
    return (u & 0x80000000u) ? ~u : (u | 0x80000000u);
}
__device__ __forceinline__ float funkey(unsigned int u) {
    return (u & 0x80000000u) ? __uint_as_float(u ^ 0x80000000u)
                             : __uint_as_float(~u);
}
#define FMA2(acc, a, b) \
    asm("fma.rn.f32x2 %0, %1, %2, %0;" : "+l"(acc) : "l"(a), "l"(b))
#define MUL2(r, a, b) \
    asm("mul.rn.f32x2 %0, %1, %2;" : "=l"(r) : "l"(a), "l"(b))
#define NEG_INF __int_as_float(0xff800000)

// -------- kernel 0: detect ts dtype + reset work counter --------
__global__ void k_detect(const unsigned int* tsw) {
    if (threadIdx.x == 0) {
        int all0 = 1;
        for (int i = 0; i < 64; i++)
            if (tsw[2 * i + 1] != 0u) { all0 = 0; break; }
        g_ts64 = all0;
        g_work = 0u;
    }
}

// -------- kernel 1: normalize queries -> transposed --------
__global__ void k_normq(const float* __restrict__ query) {
    int b = blockIdx.x;
    int d = threadIdx.x;
    float v = query[b * DDIM + d];
    float s = v * v;
    #pragma unroll
    for (int o = 16; o; o >>= 1) s += __shfl_xor_sync(0xffffffffu, s, o);
    __shared__ float ws[4];
    if ((d & 31) == 0) ws[d >> 5] = s;
    __syncthreads();
    float tot = ws[0] + ws[1] + ws[2] + ws[3];
    float n = fmaxf(sqrtf(tot), 1e-12f);
    g_qnT[d * BQ + b] = v / n;
}

// -------- kernel 2: per-key scale = decay / ||k|| --------
__global__ void k_scale(const float* __restrict__ keys, const void* ts,
                        const int* gsp, int has_gs) {
    int gw = (blockIdx.x * blockDim.x + threadIdx.x) >> 5;
    int lane = threadIdx.x & 31;
    if (gw >= NKEYS) return;
    float4 a = ((const float4*)(keys + (size_t)gw * DDIM))[lane];
    float s = a.x * a.x + a.y * a.y + a.z * a.z + a.w * a.w;
    #pragma unroll
    for (int o = 16; o; o >>= 1) s += __shfl_xor_sync(0xffffffffu, s, o);
    if (lane == 0) {
        long long t = g_ts64 ? ((const long long*)ts)[gw]
                             : (long long)((const int*)ts)[gw];
        int gs = has_gs ? gsp[0] : 1000;
        float age = (float)(gs - (int)t);
        float dec = powf(0.995f, age);
        float nr = fmaxf(sqrtf(s), 1e-12f);
        g_scale[gw] = dec / nr;
    }
}

// -------- kernel 3: persistent fused GEMM (f32x2) + chunk top-16 --------
// Conflict-free mapping: thread (tx,ty) owns queries {i*32+ty*2,+1} i=0..3
// and keys {j*32+tx*4..+3} j=0..3.
__global__ void __launch_bounds__(NTHR, 2)
k_gemm_topk(const float* __restrict__ keys) {
    extern __shared__ __align__(16) unsigned char sm[];
    float2* Qs2  = (float2*)sm;                   // [16][130] dup pairs
    float*  Ks   = (float*)(sm + OFF_KS);         // [16][132]
    float*  Sim  = (float*)sm;                    // [128][132] (union)
    float*  Ss   = (float*)(sm + OFF_SS);         // [128]
    float*  topv = (float*)(sm + OFF_TOPV);       // [128][17]
    int*    topi = (int*)(sm + OFF_TOPI);         // [128][17]
    unsigned int* swork = (unsigned int*)(sm + OFF_WORK);

    int tid = threadIdx.x;
    int tx = tid & 7;
    int ty = tid >> 3;     // 0..15

    for (;;) {
        __syncthreads();
        if (tid == 0) *swork = atomicAdd(&g_work, 1u);
        __syncthreads();
        unsigned int p = *swork;
        if (p >= NPAIRS) break;
        int chunk = p >> 3;
        int qtile = p & 7;
        int qbase = qtile * MT;
        int c0 = chunk * CHUNK;

        #pragma unroll
        for (int j = 0; j < TOPK; j++) {
            topv[tid * 17 + j] = NEG_INF;
            topi[tid * 17 + j] = 0;
        }

        for (int t0 = 0; t0 < CHUNK && c0 + t0 < NKEYS; t0 += KT) {
            int n0 = c0 + t0;
            int nk = min(KT, NKEYS - n0);
            __syncthreads();       // prior scan done (Sim union reuse)
            Ss[tid] = (n0 + tid < NKEYS) ? g_scale[n0 + tid] : 0.0f;

            unsigned long long acc[8][8];
            #pragma unroll
            for (int i = 0; i < 8; i++)
                #pragma unroll
                for (int j = 0; j < 8; j++) acc[i][j] = 0ull;

            for (int stage = 0; stage < 8; ++stage) {
                int ds = stage * 16;
                __syncthreads();
                // Q staging: coalesced LDG from g_qnT, duplicated-pair store
                {
                    int d = tid >> 3;
                    int j0 = tid & 7;
                    #pragma unroll
                    for (int i = 0; i < 4; i++) {
                        int j = j0 + 8 * i;
                        float4 v = *(const float4*)&g_qnT[(ds + d) * BQ + qbase + j * 4];
                        float2* dst = &Qs2[d * 130 + j * 4];
                        dst[0] = make_float2(v.x, v.x);
                        dst[1] = make_float2(v.y, v.y);
                        dst[2] = make_float2(v.z, v.z);
                        dst[3] = make_float2(v.w, v.w);
                    }
                }
                // K staging: 4 lanes per key row, transposed store
                {
                    int c = tid & 3;
                    int r = tid >> 2;
                    #pragma unroll
                    for (int i = 0; i < 4; i++) {
                        int row = i * 32 + r;
                        int krow = min(n0 + row, NKEYS - 1);
                        float4 v = *(const float4*)&keys[(size_t)krow * DDIM + ds + c * 4];
                        Ks[(c * 4 + 0) * 132 + row] = v.x;
                        Ks[(c * 4 + 1) * 132 + row] = v.y;
                        Ks[(c * 4 + 2) * 132 + row] = v.z;
                        Ks[(c * 4 + 3) * 132 + row] = v.w;
                    }
                }
                __syncthreads();
                #pragma unroll
                for (int d = 0; d < 16; ++d) {
                    // Q: 4 distinct 16B addrs / warp, 64B span, broadcast -> CF
                    unsigned long long qa[8];
                    const float2* qrow = Qs2 + d * 130 + ty * 2;
                    #pragma unroll
                    for (int i = 0; i < 4; i++) {
                        ulonglong2 t = *(const ulonglong2*)(qrow + i * 32);
                        qa[2 * i]     = t.x;
                        qa[2 * i + 1] = t.y;
                    }
                    // K: 8 tx x 16B tile a full 128B line -> conflict-free
                    unsigned long long kb[8];
                    const float* krow_s = Ks + d * 132 + tx * 4;
                    #pragma unroll
                    for (int j = 0; j < 4; j++) {
                        ulonglong2 t = *(const ulonglong2*)(krow_s + j * 32);
                        kb[2 * j]     = t.x;
                        kb[2 * j + 1] = t.y;
                    }
                    #pragma unroll
                    for (int i = 0; i < 8; i++)
                        #pragma unroll
                        for (int j = 0; j < 8; j++)
                            FMA2(acc[i][j], qa[i], kb[j]);
                }
            }
            __syncthreads();   // all FMAs done before Sim overwrites union

            // scale + store sims (STS.128, 16B-aligned via stride 132)
            #pragma unroll
            for (int i8 = 0; i8 < 8; i8++) {
                int q = (i8 >> 1) * 32 + ty * 2 + (i8 & 1);
                #pragma unroll
                for (int j4 = 0; j4 < 4; j4++) {
                    ulonglong2 ss2 = *(const ulonglong2*)&Ss[j4 * 32 + tx * 4];
                    ulonglong2 r;
                    MUL2(r.x, acc[i8][2 * j4],     ss2.x);
                    MUL2(r.y, acc[i8][2 * j4 + 1], ss2.y);
                    *(ulonglong2*)&Sim[q * 132 + j4 * 32 + tx * 4] = r;
                }
            }
            __syncthreads();

            // per-query scan + insertion top-16 (stride 33 words: bank-rotating)
            {
                float thr = topv[tid * 17 + TOPK - 1];
                const float* row = &Sim[tid * 132];
                for (int j = 0; j < nk; j++) {
                    float v = row[j];
                    if (v > thr) {
                        int kidx = n0 + j;
                        int pos = TOPK - 1;
                        while (pos > 0 && topv[tid * 17 + pos - 1] < v) {
                            topv[tid * 17 + pos] = topv[tid * 17 + pos - 1];
                            topi[tid * 17 + pos] = topi[tid * 17 + pos - 1];
                            pos--;
                        }
                        topv[tid * 17 + pos] = v;
                        topi[tid * 17 + pos] = kidx;
                        thr = topv[tid * 17 + TOPK - 1];
                    }
                }
            }
        }
        __syncthreads();

        {
            int b = qbase + tid;
            unsigned long long* dst = &g_cand[((size_t)b * NCHUNKS + chunk) * TOPK];
            #pragma unroll
            for (int j = 0; j < TOPK; j++) {
                unsigned long long hv =
                    (unsigned long long)fkey(topv[tid * 17 + j]) << 32;
                dst[j] = hv | (unsigned long long)(0xFFFFFFFFu -
                                (unsigned int)topi[tid * 17 + j]);
            }
        }
    }
}

// -------- kernel 4: merge candidates + weighted gather --------
#define NCAND (NCHUNKS * TOPK)

__global__ void __launch_bounds__(256)
k_merge(const float* __restrict__ values, float* __restrict__ out) {
    __shared__ unsigned long long cb[NCAND];
    __shared__ unsigned long long red[256];
    __shared__ float smv[TOPK];
    __shared__ int   sidx[TOPK];
    __shared__ float w[TOPK];

    int b = blockIdx.x, tid = threadIdx.x;
    const unsigned long long* src = &g_cand[(size_t)b * NCAND];
    for (int i = tid; i < NCAND; i += 256) cb[i] = src[i];
    __syncthreads();

    for (int r = 0; r < TOPK; r++) {
        unsigned long long m = 0ull;
        for (int i = tid; i < NCAND; i += 256) {
            unsigned long long v = cb[i];
            if (v > m) m = v;
        }
        red[tid] = m;
        __syncthreads();
        #pragma unroll
        for (int s = 128; s > 0; s >>= 1) {
            if (tid < s && red[tid + s] > red[tid]) red[tid] = red[tid + s];
            __syncthreads();
        }
        unsigned long long top = red[0];
        for (int i = tid; i < NCAND; i += 256)
            if (cb[i] == top) cb[i] = 0ull;
        if (tid == 0) {
            float s = funkey((unsigned int)(top >> 32));
            int idx = (int)(0xFFFFFFFFu - (unsigned int)(top & 0xFFFFFFFFu));
            smv[r] = (s >= 0.0f) ? s : 0.0f;
            sidx[r] = idx;
        }
        __syncthreads();
    }

    if (tid == 0) {
        float su = 0.0f;
        #pragma unroll
        for (int r = 0; r < TOPK; r++) su += smv[r];
        su += 1e-8f;
        #pragma unroll
        for (int r = 0; r < TOPK; r++) w[r] = smv[r] / su;
    }
    __syncthreads();

    if (tid < HFDIM) {
        float a = 0.0f;
        #pragma unroll
        for (int r = 0; r < TOPK; r++)
            a += w[r] * values[(size_t)sidx[r] * HFDIM + tid];
        out[(size_t)b * HFDIM + tid] = a;
    }
}

// -------- launch --------
extern "C" void kernel_launch(void* const* d_in, const int* in_sizes, int n_in,
                              void* d_out, int out_size) {
    const float* query  = (const float*)d_in[0];
    const float* keys   = (const float*)d_in[1];
    const float* values = (const float*)d_in[2];
    const void*  ts     = d_in[3];
    const int*   gsp    = (n_in > 4) ? (const int*)d_in[4] : nullptr;

    cudaFuncSetAttribute(k_gemm_topk,
                         cudaFuncAttributeMaxDynamicSharedMemorySize, SMEM_SZ);

    k_detect<<<1, 32>>>((const unsigned int*)ts);
    k_normq<<<BQ, DDIM>>>(query);
    k_scale<<<(NKEYS * 32 + 255) / 256, 256>>>(keys, ts, gsp, gsp != nullptr);
    k_gemm_topk<<<GRID_P, NTHR, SMEM_SZ>>>(keys);
    k_merge<<<BQ, 256>>>(values, (float*)d_out);
}